// round 3
// baseline (speedup 1.0000x reference)
#include <cuda_runtime.h>
#include <cstdint>
#include <cstddef>

// Problem constants
#define BATCH   2
#define SEQ     2048
#define EMBED   1024
#define HEADS   16
#define HDIM    64
#define MTOT    (BATCH * SEQ)          // 4096
#define OUT_ELEMS   ((size_t)BATCH * SEQ * EMBED)                    // 4,194,304
#define ATTN_ELEMS  ((size_t)BATCH * HEADS * SEQ * SEQ)              // 134,217,728

// Scratch: projected Q/K/V in [B,H,S,Dh] layout, and merged attention output [B,S,E]
__device__ float g_Q[BATCH * HEADS * SEQ * HDIM];
__device__ float g_K[BATCH * HEADS * SEQ * HDIM];
__device__ float g_V[BATCH * HEADS * SEQ * HDIM];
__device__ float g_AO[BATCH * SEQ * EMBED];

// ---------------------------------------------------------------------------
// Kernel 1/5: C[M,N] = A[M,K] @ W[N,K]^T + bias, M=4096, N=K=1024.
// 128x128 block tile, BK=8, 256 threads, 8x8 micro-tile.
// split==1: store into dst as [B,H,S,Dh] (head split); split==0: plain [M,N].
// ---------------------------------------------------------------------------
__global__ __launch_bounds__(256) void proj_kernel(
    const float* __restrict__ A, const float* __restrict__ W,
    const float* __restrict__ bias, float* __restrict__ dst, int split)
{
    __shared__ float As[8][128];
    __shared__ float Bs[8][128];

    const int tid = threadIdx.x;
    const int bm  = blockIdx.y * 128;
    const int bn  = blockIdx.x * 128;

    const int lrow = tid >> 1;          // 0..127
    const int lcol = (tid & 1) * 4;     // 0 or 4
    const int ty   = tid >> 4;          // 0..15 -> rows ty*8..+7
    const int tx   = tid & 15;          // 0..15 -> cols tx*8..+7

    float acc[8][8];
#pragma unroll
    for (int i = 0; i < 8; ++i)
#pragma unroll
        for (int j = 0; j < 8; ++j) acc[i][j] = 0.0f;

    const float* aptr = A + (size_t)(bm + lrow) * EMBED + lcol;
    const float* wptr = W + (size_t)(bn + lrow) * EMBED + lcol;

    for (int kt = 0; kt < EMBED; kt += 8) {
        float4 av = *(const float4*)(aptr + kt);
        float4 wv = *(const float4*)(wptr + kt);
        As[lcol + 0][lrow] = av.x; As[lcol + 1][lrow] = av.y;
        As[lcol + 2][lrow] = av.z; As[lcol + 3][lrow] = av.w;
        Bs[lcol + 0][lrow] = wv.x; Bs[lcol + 1][lrow] = wv.y;
        Bs[lcol + 2][lrow] = wv.z; Bs[lcol + 3][lrow] = wv.w;
        __syncthreads();
#pragma unroll
        for (int kk = 0; kk < 8; ++kk) {
            float ra[8], rb[8];
            *(float4*)(ra)     = *(const float4*)&As[kk][ty * 8];
            *(float4*)(ra + 4) = *(const float4*)&As[kk][ty * 8 + 4];
            *(float4*)(rb)     = *(const float4*)&Bs[kk][tx * 8];
            *(float4*)(rb + 4) = *(const float4*)&Bs[kk][tx * 8 + 4];
#pragma unroll
            for (int i = 0; i < 8; ++i)
#pragma unroll
                for (int j = 0; j < 8; ++j)
                    acc[i][j] += ra[i] * rb[j];
        }
        __syncthreads();
    }

    const int n0 = bn + tx * 8;
    const float4 bb0 = *(const float4*)&bias[n0];
    const float4 bb1 = *(const float4*)&bias[n0 + 4];

#pragma unroll
    for (int i = 0; i < 8; ++i) {
        const int m = bm + ty * 8 + i;
        float4 v0 = make_float4(acc[i][0] + bb0.x, acc[i][1] + bb0.y,
                                acc[i][2] + bb0.z, acc[i][3] + bb0.w);
        float4 v1 = make_float4(acc[i][4] + bb1.x, acc[i][5] + bb1.y,
                                acc[i][6] + bb1.z, acc[i][7] + bb1.w);
        if (split) {
            const int b = m >> 11, s = m & 2047;
            const int h = n0 >> 6, d = n0 & 63;
            float* p = dst + ((size_t)(b * HEADS + h) * SEQ + s) * HDIM + d;
            *(float4*)(p)     = v0;
            *(float4*)(p + 4) = v1;
        } else {
            float* p = dst + (size_t)m * EMBED + n0;
            *(float4*)(p)     = v0;
            *(float4*)(p + 4) = v1;
        }
    }
}

// ---------------------------------------------------------------------------
// Kernel 2: raw scores S[z][q][k] = (Q_z[q,:] . K_z[k,:]) * 1/sqrt(64)
// per z = b*16+h. 128x128 tile, BK=8 over K=64.
// ---------------------------------------------------------------------------
__global__ __launch_bounds__(256) void scores_kernel(
    const float* __restrict__ Qg, const float* __restrict__ Kg,
    float* __restrict__ attn)
{
    __shared__ float As[8][128];
    __shared__ float Bs[8][128];

    const int tid = threadIdx.x;
    const int z   = blockIdx.z;
    const int bm  = blockIdx.y * 128;   // q tile
    const int bn  = blockIdx.x * 128;   // k tile

    const float* Aq = Qg + (size_t)z * SEQ * HDIM;
    const float* Bk = Kg + (size_t)z * SEQ * HDIM;

    const int lrow = tid >> 1;
    const int lcol = (tid & 1) * 4;
    const int ty = tid >> 4;
    const int tx = tid & 15;

    float acc[8][8];
#pragma unroll
    for (int i = 0; i < 8; ++i)
#pragma unroll
        for (int j = 0; j < 8; ++j) acc[i][j] = 0.0f;

    const float* aptr = Aq + (size_t)(bm + lrow) * HDIM + lcol;
    const float* bptr = Bk + (size_t)(bn + lrow) * HDIM + lcol;

    for (int kt = 0; kt < HDIM; kt += 8) {
        float4 av = *(const float4*)(aptr + kt);
        float4 bv = *(const float4*)(bptr + kt);
        As[lcol + 0][lrow] = av.x; As[lcol + 1][lrow] = av.y;
        As[lcol + 2][lrow] = av.z; As[lcol + 3][lrow] = av.w;
        Bs[lcol + 0][lrow] = bv.x; Bs[lcol + 1][lrow] = bv.y;
        Bs[lcol + 2][lrow] = bv.z; Bs[lcol + 3][lrow] = bv.w;
        __syncthreads();
#pragma unroll
        for (int kk = 0; kk < 8; ++kk) {
            float ra[8], rb[8];
            *(float4*)(ra)     = *(const float4*)&As[kk][ty * 8];
            *(float4*)(ra + 4) = *(const float4*)&As[kk][ty * 8 + 4];
            *(float4*)(rb)     = *(const float4*)&Bs[kk][tx * 8];
            *(float4*)(rb + 4) = *(const float4*)&Bs[kk][tx * 8 + 4];
#pragma unroll
            for (int i = 0; i < 8; ++i)
#pragma unroll
                for (int j = 0; j < 8; ++j)
                    acc[i][j] += ra[i] * rb[j];
        }
        __syncthreads();
    }

    const float scale = 0.125f;  // 1/sqrt(64)
    float* base = attn + (size_t)z * SEQ * SEQ;
#pragma unroll
    for (int i = 0; i < 8; ++i) {
        const int q = bm + ty * 8 + i;
        float* p = base + (size_t)q * SEQ + bn + tx * 8;
        float4 v0 = make_float4(acc[i][0] * scale, acc[i][1] * scale,
                                acc[i][2] * scale, acc[i][3] * scale);
        float4 v1 = make_float4(acc[i][4] * scale, acc[i][5] * scale,
                                acc[i][6] * scale, acc[i][7] * scale);
        *(float4*)(p)     = v0;
        *(float4*)(p + 4) = v1;
    }
}

// ---------------------------------------------------------------------------
// Kernel 3: in-place softmax over rows of 2048. One CTA (256 thr) per row,
// 8 elems/thread held in registers across both reduction phases -> 1R + 1W.
// ---------------------------------------------------------------------------
__global__ __launch_bounds__(256) void softmax_kernel(float* __restrict__ attn)
{
    const size_t row = blockIdx.x;
    float* p = attn + row * SEQ;
    const int t = threadIdx.x;

    float x[8];
    *(float4*)(x)     = ((const float4*)p)[2 * t];
    *(float4*)(x + 4) = ((const float4*)p)[2 * t + 1];

    __shared__ float sred[8];
    const int lane = t & 31;
    const int wid  = t >> 5;

    float m = x[0];
#pragma unroll
    for (int i = 1; i < 8; ++i) m = fmaxf(m, x[i]);
#pragma unroll
    for (int o = 16; o > 0; o >>= 1)
        m = fmaxf(m, __shfl_xor_sync(0xffffffffu, m, o));
    if (lane == 0) sred[wid] = m;
    __syncthreads();
    m = sred[0];
#pragma unroll
    for (int w = 1; w < 8; ++w) m = fmaxf(m, sred[w]);
    __syncthreads();

    float s = 0.0f;
#pragma unroll
    for (int i = 0; i < 8; ++i) {
        x[i] = __expf(x[i] - m);
        s += x[i];
    }
#pragma unroll
    for (int o = 16; o > 0; o >>= 1)
        s += __shfl_xor_sync(0xffffffffu, s, o);
    if (lane == 0) sred[wid] = s;
    __syncthreads();
    s = 0.0f;
#pragma unroll
    for (int w = 0; w < 8; ++w) s += sred[w];

    const float inv = 1.0f / s;
#pragma unroll
    for (int i = 0; i < 8; ++i) x[i] *= inv;
    ((float4*)p)[2 * t]     = *(float4*)(x);
    ((float4*)p)[2 * t + 1] = *(float4*)(x + 4);
}

// ---------------------------------------------------------------------------
// Kernel 4: AO[z][q][:] = sum_k W[z][q][k] * V[z][k][:]  (N=64)
// 128x64 tile, BK=16, 256 threads, 8x4 micro-tile. Stores merged-head layout.
// ---------------------------------------------------------------------------
__global__ __launch_bounds__(256) void av_kernel(
    const float* __restrict__ attn, const float* __restrict__ Vg,
    float* __restrict__ ao)
{
    __shared__ float As[16][128];
    __shared__ float Bs[16][64];

    const int tid = threadIdx.x;
    const int z   = blockIdx.y;
    const int bm  = blockIdx.x * 128;

    const float* Wp = attn + (size_t)z * SEQ * SEQ;
    const float* Vp = Vg + (size_t)z * SEQ * HDIM;

    const int arow = tid >> 1;          // 0..127
    const int acol = (tid & 1) * 8;     // 0 or 8
    const int brow = tid >> 4;          // 0..15
    const int bcol = (tid & 15) * 4;    // 0..60
    const int ty = tid >> 4;            // rows ty*8..+7
    const int tx = tid & 15;            // cols tx*4..+3

    float acc[8][4];
#pragma unroll
    for (int i = 0; i < 8; ++i)
#pragma unroll
        for (int j = 0; j < 4; ++j) acc[i][j] = 0.0f;

    const float* aptr = Wp + (size_t)(bm + arow) * SEQ + acol;
    const float* bptr = Vp + (size_t)brow * HDIM + bcol;

    for (int kt = 0; kt < SEQ; kt += 16) {
        float4 a0 = *(const float4*)(aptr + kt);
        float4 a1 = *(const float4*)(aptr + kt + 4);
        As[acol + 0][arow] = a0.x; As[acol + 1][arow] = a0.y;
        As[acol + 2][arow] = a0.z; As[acol + 3][arow] = a0.w;
        As[acol + 4][arow] = a1.x; As[acol + 5][arow] = a1.y;
        As[acol + 6][arow] = a1.z; As[acol + 7][arow] = a1.w;
        float4 bv = *(const float4*)(bptr + (size_t)kt * HDIM);
        *(float4*)&Bs[brow][bcol] = bv;
        __syncthreads();
#pragma unroll
        for (int kk = 0; kk < 16; ++kk) {
            float ra[8], rb[4];
            *(float4*)(ra)     = *(const float4*)&As[kk][ty * 8];
            *(float4*)(ra + 4) = *(const float4*)&As[kk][ty * 8 + 4];
            *(float4*)(rb)     = *(const float4*)&Bs[kk][tx * 4];
#pragma unroll
            for (int i = 0; i < 8; ++i)
#pragma unroll
                for (int j = 0; j < 4; ++j)
                    acc[i][j] += ra[i] * rb[j];
        }
        __syncthreads();
    }

    const int b = z >> 4, h = z & 15;
#pragma unroll
    for (int i = 0; i < 8; ++i) {
        const int q = bm + ty * 8 + i;
        float* p = ao + ((size_t)(b * SEQ + q)) * EMBED + h * HDIM + tx * 4;
        *(float4*)p = make_float4(acc[i][0], acc[i][1], acc[i][2], acc[i][3]);
    }
}

// ---------------------------------------------------------------------------
// launch
// ---------------------------------------------------------------------------
extern "C" void kernel_launch(void* const* d_in, const int* in_sizes, int n_in,
                              void* d_out, int out_size)
{
    (void)in_sizes; (void)n_in; (void)out_size;
    const float* query = (const float*)d_in[0];
    const float* key   = (const float*)d_in[1];
    const float* value = (const float*)d_in[2];
    const float* q_w   = (const float*)d_in[3];
    const float* q_b   = (const float*)d_in[4];
    const float* k_w   = (const float*)d_in[5];
    const float* k_b   = (const float*)d_in[6];
    const float* v_w   = (const float*)d_in[7];
    const float* v_b   = (const float*)d_in[8];
    const float* o_w   = (const float*)d_in[9];
    const float* o_b   = (const float*)d_in[10];

    float* out  = (float*)d_out;                 // [B,S,E]
    float* attn = out + OUT_ELEMS;               // [B,H,S,S]

    float *pQ, *pK, *pV, *pAO;
    cudaGetSymbolAddress((void**)&pQ, g_Q);
    cudaGetSymbolAddress((void**)&pK, g_K);
    cudaGetSymbolAddress((void**)&pV, g_V);
    cudaGetSymbolAddress((void**)&pAO, g_AO);

    // 1) QKV projections (split-head stores)
    dim3 pgrid(EMBED / 128, MTOT / 128);         // (8, 32)
    proj_kernel<<<pgrid, 256>>>(query, q_w, q_b, pQ, 1);
    proj_kernel<<<pgrid, 256>>>(key,   k_w, k_b, pK, 1);
    proj_kernel<<<pgrid, 256>>>(value, v_w, v_b, pV, 1);

    // 2) raw scaled scores into attn area
    dim3 sgrid(SEQ / 128, SEQ / 128, BATCH * HEADS);  // (16,16,32)
    scores_kernel<<<sgrid, 256>>>(pQ, pK, attn);

    // 3) softmax in place (one CTA per row)
    softmax_kernel<<<(unsigned)(BATCH * HEADS * SEQ), 256>>>(attn);

    // 4) attn @ V -> merged heads
    dim3 avgrid(SEQ / 128, BATCH * HEADS);       // (16, 32)
    av_kernel<<<avgrid, 256>>>(attn, pV, pAO);

    // 5) output projection (plain store)
    proj_kernel<<<pgrid, 256>>>(pAO, o_w, o_b, out, 0);
}

// round 7
// speedup vs baseline: 1.6878x; 1.6878x over previous
#include <cuda_runtime.h>
#include <cuda_bf16.h>
#include <cstdint>
#include <cstddef>

// Problem constants
#define BATCH   2
#define SEQ     2048
#define EMBED   1024
#define HEADS   16
#define HDIM    64
#define MTOT    (BATCH * SEQ)          // 4096
#define OUT_ELEMS   ((size_t)BATCH * SEQ * EMBED)                    // 4,194,304

// Scratch
__device__ float g_Q[BATCH * HEADS * SEQ * HDIM];
__device__ float g_K[BATCH * HEADS * SEQ * HDIM];
__device__ float g_V[BATCH * HEADS * SEQ * HDIM];
__device__ float g_AO[BATCH * SEQ * EMBED];

// ===========================================================================
// helpers
// ===========================================================================
__device__ __forceinline__ uint32_t pack_bf16x2(__nv_bfloat16 a, __nv_bfloat16 b) {
    __nv_bfloat162 t;
    t.x = a; t.y = b;
    return *reinterpret_cast<uint32_t*>(&t);
}

// hi/lo split of a float4 -> two u32 each (pairs along k)
__device__ __forceinline__ void cvt_store_hl(uint32_t* hi, uint32_t* lo, float4 v) {
    __nv_bfloat16 hx = __float2bfloat16(v.x);
    __nv_bfloat16 hy = __float2bfloat16(v.y);
    __nv_bfloat16 hz = __float2bfloat16(v.z);
    __nv_bfloat16 hw = __float2bfloat16(v.w);
    hi[0] = pack_bf16x2(hx, hy);
    hi[1] = pack_bf16x2(hz, hw);
    lo[0] = pack_bf16x2(__float2bfloat16(v.x - __bfloat162float(hx)),
                        __float2bfloat16(v.y - __bfloat162float(hy)));
    lo[1] = pack_bf16x2(__float2bfloat16(v.z - __bfloat162float(hz)),
                        __float2bfloat16(v.w - __bfloat162float(hw)));
}

// mma.sync m16n8k16 bf16 -> f32, C += A*B
__device__ __forceinline__ void mma16816(float* c, const uint32_t* a, const uint32_t* b) {
    asm volatile(
        "mma.sync.aligned.m16n8k16.row.col.f32.bf16.bf16.f32 "
        "{%0,%1,%2,%3}, {%4,%5,%6,%7}, {%8,%9}, {%0,%1,%2,%3};\n"
        : "+f"(c[0]), "+f"(c[1]), "+f"(c[2]), "+f"(c[3])
        : "r"(a[0]), "r"(a[1]), "r"(a[2]), "r"(a[3]), "r"(b[0]), "r"(b[1]));
}

// smem row stride in u32 for BK=32 tiles: 16 data + 4 pad -> (20*r + c) % 32
// is conflict-free over the fragment access pattern.
#define SK 20

// ===========================================================================
// Unified split-bf16 GEMM:  C[M,N] = A[M,Kd] * B[N,Kd]^T   (both K-major)
// CTA tile 128x128, BK=32, 256 threads (8 warps as 2m x 4n, warp tile 64x32).
// mode 0: C[r*ldc+n] = acc + bias[n]
// mode 1: split-head store to [B,H,S,Dh], + bias[n]
// mode 2: C[r*ldc+n] = acc * scale           (no bias)
// z (blockIdx.z) offsets A/B/C by sAz/sBz/sCz.
// ===========================================================================
__global__ __launch_bounds__(256, 1) void gemm_bf16s_kernel(
    const float* __restrict__ Ag, const float* __restrict__ Bg,
    const float* __restrict__ bias, float* __restrict__ Cg,
    int lda, int ldb, int ldc, int kdim,
    size_t sAz, size_t sBz, size_t sCz,
    int mode, float scale)
{
    __shared__ uint32_t Ah[128 * SK], Al[128 * SK], Bh[128 * SK], Bl[128 * SK];

    const int tid = threadIdx.x;
    const int w   = tid >> 5;
    const int lid = tid & 31;
    const int g   = lid >> 2;      // 0..7
    const int tg  = lid & 3;       // 0..3
    const int wm  = w >> 2;        // 0..1
    const int wn  = w & 3;         // 0..3

    const int z  = blockIdx.z;
    const int bm = blockIdx.y * 128;
    const int bn = blockIdx.x * 128;

    const float* A = Ag + (size_t)z * sAz;
    const float* B = Bg + (size_t)z * sBz;
    float*       C = Cg + (size_t)z * sCz;

    // staging mapping: 2 threads per row, 16 elems (8 u32) each
    const int srow = tid >> 1;            // 0..127
    const int su   = (tid & 1) * 8;       // u32 offset in row
    const float* ap = A + (size_t)(bm + srow) * lda + su * 2;
    const float* bp = B + (size_t)(bn + srow) * ldb + su * 2;

    float c[4][4][4];
#pragma unroll
    for (int mt = 0; mt < 4; ++mt)
#pragma unroll
        for (int nt = 0; nt < 4; ++nt)
#pragma unroll
            for (int i = 0; i < 4; ++i) c[mt][nt][i] = 0.0f;

    // prefetch first k-slab
    float4 pa[4], pb[4];
#pragma unroll
    for (int j = 0; j < 4; ++j) {
        pa[j] = *(const float4*)(ap + j * 4);
        pb[j] = *(const float4*)(bp + j * 4);
    }

    for (int kt = 0; kt < kdim; kt += 32) {
        // store prefetched slab to smem (hi/lo split)
#pragma unroll
        for (int j = 0; j < 4; ++j) {
            cvt_store_hl(&Ah[srow * SK + su + j * 2], &Al[srow * SK + su + j * 2], pa[j]);
            cvt_store_hl(&Bh[srow * SK + su + j * 2], &Bl[srow * SK + su + j * 2], pb[j]);
        }
        __syncthreads();

        // prefetch next slab (overlaps with MMA below)
        if (kt + 32 < kdim) {
#pragma unroll
            for (int j = 0; j < 4; ++j) {
                pa[j] = *(const float4*)(ap + kt + 32 + j * 4);
                pb[j] = *(const float4*)(bp + kt + 32 + j * 4);
            }
        }

        // compute: 2 x k16 steps
#pragma unroll
        for (int k16 = 0; k16 < 2; ++k16) {
            const int kb = k16 * 8 + tg;
            uint32_t ah[4][4], al[4][4], bh[4][2], bl[4][2];
#pragma unroll
            for (int mt = 0; mt < 4; ++mt) {
                const int r = (wm * 64 + mt * 16 + g) * SK + kb;
                ah[mt][0] = Ah[r];              ah[mt][1] = Ah[r + 8 * SK];
                ah[mt][2] = Ah[r + 4];          ah[mt][3] = Ah[r + 8 * SK + 4];
                al[mt][0] = Al[r];              al[mt][1] = Al[r + 8 * SK];
                al[mt][2] = Al[r + 4];          al[mt][3] = Al[r + 8 * SK + 4];
            }
#pragma unroll
            for (int nt = 0; nt < 4; ++nt) {
                const int r = (wn * 32 + nt * 8 + g) * SK + kb;
                bh[nt][0] = Bh[r];  bh[nt][1] = Bh[r + 4];
                bl[nt][0] = Bl[r];  bl[nt][1] = Bl[r + 4];
            }
#pragma unroll
            for (int mt = 0; mt < 4; ++mt)
#pragma unroll
                for (int nt = 0; nt < 4; ++nt) {
                    mma16816(c[mt][nt], ah[mt], bh[nt]);
                    mma16816(c[mt][nt], ah[mt], bl[nt]);
                    mma16816(c[mt][nt], al[mt], bh[nt]);
                }
        }
        __syncthreads();
    }

    // epilogue
#pragma unroll
    for (int mt = 0; mt < 4; ++mt) {
#pragma unroll
        for (int nt = 0; nt < 4; ++nt) {
            const int r0 = bm + wm * 64 + mt * 16 + g;
            const int n0 = bn + wn * 32 + nt * 8 + tg * 2;
            float2 v0 = make_float2(c[mt][nt][0], c[mt][nt][1]);
            float2 v1 = make_float2(c[mt][nt][2], c[mt][nt][3]);
            if (mode == 2) {
                v0.x *= scale; v0.y *= scale;
                v1.x *= scale; v1.y *= scale;
                float* p0 = C + (size_t)r0 * ldc + n0;
                float* p1 = C + (size_t)(r0 + 8) * ldc + n0;
                *(float2*)p0 = v0;
                *(float2*)p1 = v1;
            } else {
                const float2 bb = *(const float2*)&bias[n0];
                v0.x += bb.x; v0.y += bb.y;
                v1.x += bb.x; v1.y += bb.y;
                if (mode == 1) {
                    const int h = n0 >> 6, d = n0 & 63;
                    const int b0 = r0 >> 11, s0 = r0 & 2047;
                    const int b1 = (r0 + 8) >> 11, s1 = (r0 + 8) & 2047;
                    float* p0 = C + ((size_t)(b0 * HEADS + h) * SEQ + s0) * HDIM + d;
                    float* p1 = C + ((size_t)(b1 * HEADS + h) * SEQ + s1) * HDIM + d;
                    *(float2*)p0 = v0;
                    *(float2*)p1 = v1;
                } else {
                    float* p0 = C + (size_t)r0 * ldc + n0;
                    float* p1 = C + (size_t)(r0 + 8) * ldc + n0;
                    *(float2*)p0 = v0;
                    *(float2*)p1 = v1;
                }
            }
        }
    }
}

// ===========================================================================
// av: AO[z][q][d] = sum_k attn[z][q][k] * V[z][k][d]
// CTA tile 128(q) x 64(d), BK=32, 8 warps as 4m x 2n, warp tile 32x32.
// V is staged transposed (Bs[n=d][k]) with hi/lo split.
// ===========================================================================
__global__ __launch_bounds__(256, 1) void av_mma_kernel(
    const float* __restrict__ attn, const float* __restrict__ Vg,
    float* __restrict__ ao)
{
    __shared__ uint32_t Ah[128 * SK], Al[128 * SK], Bh[64 * SK], Bl[64 * SK];

    const int tid = threadIdx.x;
    const int w   = tid >> 5;
    const int lid = tid & 31;
    const int g   = lid >> 2;
    const int tg  = lid & 3;
    const int wm  = w >> 1;        // 0..3
    const int wn  = w & 1;         // 0..1

    const int z  = blockIdx.y;
    const int bm = blockIdx.x * 128;

    const float* Wp = attn + (size_t)z * SEQ * SEQ + (size_t)bm * SEQ;
    const float* Vp = Vg + (size_t)z * SEQ * HDIM;

    const int srow = tid >> 1;
    const int su   = (tid & 1) * 8;
    const float* ap = Wp + (size_t)srow * SEQ + su * 2;

    const int vn  = tid & 63;      // d index
    const int kp0 = tid >> 6;      // 0..3

    float c[2][4][4];
#pragma unroll
    for (int mt = 0; mt < 2; ++mt)
#pragma unroll
        for (int nt = 0; nt < 4; ++nt)
#pragma unroll
            for (int i = 0; i < 4; ++i) c[mt][nt][i] = 0.0f;

    float4 pa[4];
    float  pv[8];
#pragma unroll
    for (int j = 0; j < 4; ++j) pa[j] = *(const float4*)(ap + j * 4);
#pragma unroll
    for (int p = 0; p < 4; ++p) {
        const int kp = p * 4 + kp0;
        pv[p * 2]     = Vp[(size_t)(kp * 2) * HDIM + vn];
        pv[p * 2 + 1] = Vp[(size_t)(kp * 2 + 1) * HDIM + vn];
    }

    for (int kt = 0; kt < SEQ; kt += 32) {
        // stage A (attn rows) hi/lo
#pragma unroll
        for (int j = 0; j < 4; ++j)
            cvt_store_hl(&Ah[srow * SK + su + j * 2], &Al[srow * SK + su + j * 2], pa[j]);
        // stage B (V transposed) hi/lo
#pragma unroll
        for (int p = 0; p < 4; ++p) {
            const int kp = p * 4 + kp0;
            const float v0 = pv[p * 2], v1 = pv[p * 2 + 1];
            __nv_bfloat16 h0 = __float2bfloat16(v0);
            __nv_bfloat16 h1 = __float2bfloat16(v1);
            Bh[vn * SK + kp] = pack_bf16x2(h0, h1);
            Bl[vn * SK + kp] = pack_bf16x2(
                __float2bfloat16(v0 - __bfloat162float(h0)),
                __float2bfloat16(v1 - __bfloat162float(h1)));
        }
        __syncthreads();

        // prefetch next slab
        if (kt + 32 < SEQ) {
#pragma unroll
            for (int j = 0; j < 4; ++j)
                pa[j] = *(const float4*)(ap + kt + 32 + j * 4);
#pragma unroll
            for (int p = 0; p < 4; ++p) {
                const int kp = p * 4 + kp0;
                pv[p * 2]     = Vp[(size_t)(kt + 32 + kp * 2) * HDIM + vn];
                pv[p * 2 + 1] = Vp[(size_t)(kt + 32 + kp * 2 + 1) * HDIM + vn];
            }
        }

#pragma unroll
        for (int k16 = 0; k16 < 2; ++k16) {
            const int kb = k16 * 8 + tg;
            uint32_t ah[2][4], al[2][4], bh[4][2], bl[4][2];
#pragma unroll
            for (int mt = 0; mt < 2; ++mt) {
                const int r = (wm * 32 + mt * 16 + g) * SK + kb;
                ah[mt][0] = Ah[r];     ah[mt][1] = Ah[r + 8 * SK];
                ah[mt][2] = Ah[r + 4]; ah[mt][3] = Ah[r + 8 * SK + 4];
                al[mt][0] = Al[r];     al[mt][1] = Al[r + 8 * SK];
                al[mt][2] = Al[r + 4]; al[mt][3] = Al[r + 8 * SK + 4];
            }
#pragma unroll
            for (int nt = 0; nt < 4; ++nt) {
                const int r = (wn * 32 + nt * 8 + g) * SK + kb;
                bh[nt][0] = Bh[r];  bh[nt][1] = Bh[r + 4];
                bl[nt][0] = Bl[r];  bl[nt][1] = Bl[r + 4];
            }
#pragma unroll
            for (int mt = 0; mt < 2; ++mt)
#pragma unroll
                for (int nt = 0; nt < 4; ++nt) {
                    mma16816(c[mt][nt], ah[mt], bh[nt]);
                    mma16816(c[mt][nt], ah[mt], bl[nt]);
                    mma16816(c[mt][nt], al[mt], bh[nt]);
                }
        }
        __syncthreads();
    }

    const int b = z >> 4, h = z & 15;
#pragma unroll
    for (int mt = 0; mt < 2; ++mt) {
#pragma unroll
        for (int nt = 0; nt < 4; ++nt) {
            const int q0 = bm + wm * 32 + mt * 16 + g;
            const int d0 = wn * 32 + nt * 8 + tg * 2;
            float* p0 = ao + ((size_t)(b * SEQ + q0)) * EMBED + h * HDIM + d0;
            float* p1 = ao + ((size_t)(b * SEQ + q0 + 8)) * EMBED + h * HDIM + d0;
            *(float2*)p0 = make_float2(c[mt][nt][0], c[mt][nt][1]);
            *(float2*)p1 = make_float2(c[mt][nt][2], c[mt][nt][3]);
        }
    }
}

// ---------------------------------------------------------------------------
// Softmax: in-place over rows of 2048. One CTA (256 thr) per row.
// ---------------------------------------------------------------------------
__global__ __launch_bounds__(256) void softmax_kernel(float* __restrict__ attn)
{
    const size_t row = blockIdx.x;
    float* p = attn + row * SEQ;
    const int t = threadIdx.x;

    float x[8];
    *(float4*)(x)     = ((const float4*)p)[2 * t];
    *(float4*)(x + 4) = ((const float4*)p)[2 * t + 1];

    __shared__ float sred[8];
    const int lane = t & 31;
    const int wid  = t >> 5;

    float m = x[0];
#pragma unroll
    for (int i = 1; i < 8; ++i) m = fmaxf(m, x[i]);
#pragma unroll
    for (int o = 16; o > 0; o >>= 1)
        m = fmaxf(m, __shfl_xor_sync(0xffffffffu, m, o));
    if (lane == 0) sred[wid] = m;
    __syncthreads();
    m = sred[0];
#pragma unroll
    for (int w = 1; w < 8; ++w) m = fmaxf(m, sred[w]);
    __syncthreads();

    float s = 0.0f;
#pragma unroll
    for (int i = 0; i < 8; ++i) {
        x[i] = __expf(x[i] - m);
        s += x[i];
    }
#pragma unroll
    for (int o = 16; o > 0; o >>= 1)
        s += __shfl_xor_sync(0xffffffffu, s, o);
    if (lane == 0) sred[wid] = s;
    __syncthreads();
    s = 0.0f;
#pragma unroll
    for (int w = 0; w < 8; ++w) s += sred[w];

    const float inv = 1.0f / s;
#pragma unroll
    for (int i = 0; i < 8; ++i) x[i] *= inv;
    ((float4*)p)[2 * t]     = *(float4*)(x);
    ((float4*)p)[2 * t + 1] = *(float4*)(x + 4);
}

// ---------------------------------------------------------------------------
// launch
// ---------------------------------------------------------------------------
extern "C" void kernel_launch(void* const* d_in, const int* in_sizes, int n_in,
                              void* d_out, int out_size)
{
    (void)in_sizes; (void)n_in; (void)out_size;
    const float* query = (const float*)d_in[0];
    const float* key   = (const float*)d_in[1];
    const float* value = (const float*)d_in[2];
    const float* q_w   = (const float*)d_in[3];
    const float* q_b   = (const float*)d_in[4];
    const float* k_w   = (const float*)d_in[5];
    const float* k_b   = (const float*)d_in[6];
    const float* v_w   = (const float*)d_in[7];
    const float* v_b   = (const float*)d_in[8];
    const float* o_w   = (const float*)d_in[9];
    const float* o_b   = (const float*)d_in[10];

    float* out  = (float*)d_out;                 // [B,S,E]
    float* attn = out + OUT_ELEMS;               // [B,H,S,S]

    float *pQ, *pK, *pV, *pAO;
    cudaGetSymbolAddress((void**)&pQ, g_Q);
    cudaGetSymbolAddress((void**)&pK, g_K);
    cudaGetSymbolAddress((void**)&pV, g_V);
    cudaGetSymbolAddress((void**)&pAO, g_AO);

    // 1) QKV projections: C = X @ W^T + b, split-head stores (mode 1)
    dim3 pgrid(EMBED / 128, MTOT / 128, 1);      // (8, 32)
    gemm_bf16s_kernel<<<pgrid, 256>>>(query, q_w, q_b, pQ,
                                      EMBED, EMBED, 0, EMBED, 0, 0, 0, 1, 1.0f);
    gemm_bf16s_kernel<<<pgrid, 256>>>(key, k_w, k_b, pK,
                                      EMBED, EMBED, 0, EMBED, 0, 0, 0, 1, 1.0f);
    gemm_bf16s_kernel<<<pgrid, 256>>>(value, v_w, v_b, pV,
                                      EMBED, EMBED, 0, EMBED, 0, 0, 0, 1, 1.0f);

    // 2) scores: attn[z] = (Q_z @ K_z^T) * 0.125 (mode 2)
    dim3 sgrid(SEQ / 128, SEQ / 128, BATCH * HEADS);  // (16, 16, 32)
    gemm_bf16s_kernel<<<sgrid, 256>>>(pQ, pK, nullptr, attn,
                                      HDIM, HDIM, SEQ, HDIM,
                                      (size_t)SEQ * HDIM, (size_t)SEQ * HDIM,
                                      (size_t)SEQ * SEQ, 2, 0.125f);

    // 3) softmax in place
    softmax_kernel<<<(unsigned)(BATCH * HEADS * SEQ), 256>>>(attn);

    // 4) attn @ V -> merged heads
    dim3 avgrid(SEQ / 128, BATCH * HEADS);       // (16, 32)
    av_mma_kernel<<<avgrid, 256>>>(attn, pV, pAO);

    // 5) output projection (plain store, mode 0)
    gemm_bf16s_kernel<<<pgrid, 256>>>(pAO, o_w, o_b, out,
                                      EMBED, EMBED, EMBED, EMBED, 0, 0, 0, 0, 1.0f);
}